// round 2
// baseline (speedup 1.0000x reference)
#include <cuda_runtime.h>
#include <cuda_bf16.h>
#include <cstdint>

// ---------------------------------------------------------------------------
// Problem constants: B=2048, T=2, N(tokens)=64, C=256, H=8, hd=32
// ---------------------------------------------------------------------------
#define B_SZ   2048
#define T_SZ   2
#define NTOK   64
#define CDIM   256
#define NHEAD  8
#define HDIM   32

// Scratch (allocation-free contract: __device__ globals)
__device__ float g_q   [33554432];    // (B*N, C)        = 131072 x 256
__device__ float g_kv  [134217728];   // (B*T*N, 2C)     = 262144 x 512
__device__ float g_att [67108864];    // (B*T*N, C)      = 262144 x 256
__device__ float g_bias[32768];       // (H, N, N)       = 8 x 64 x 64

// ---------------------------------------------------------------------------
// Helpers
// ---------------------------------------------------------------------------
__device__ __forceinline__ float tf32r(float x) {
    uint32_t u;
    asm("cvt.rna.tf32.f32 %0, %1;" : "=r"(u) : "f"(x));
    return __uint_as_float(u);
}

__device__ __forceinline__ void mma_tf32(float (&d)[4], const uint32_t (&a)[4],
                                         uint32_t b0, uint32_t b1) {
    asm volatile(
        "mma.sync.aligned.m16n8k8.row.col.f32.tf32.tf32.f32 "
        "{%0,%1,%2,%3}, {%4,%5,%6,%7}, {%8,%9}, {%0,%1,%2,%3};\n"
        : "+f"(d[0]), "+f"(d[1]), "+f"(d[2]), "+f"(d[3])
        : "r"(a[0]), "r"(a[1]), "r"(a[2]), "r"(a[3]), "r"(b0), "r"(b1));
}

// ---------------------------------------------------------------------------
// Relative position bias table -> dense (H, 64, 64)
// ---------------------------------------------------------------------------
__global__ void bias_kernel(const float* __restrict__ rpb) {
    int n = blockIdx.x;    // 0..63 (query token)
    int m = threadIdx.x;   // 0..63 (key token)
    int in_ = n >> 3, jn = n & 7;
    int im  = m >> 3, jm = m & 7;
    int idx = (in_ - im + 7) * 15 + (jn - jm + 7);
#pragma unroll
    for (int h = 0; h < NHEAD; h++)
        g_bias[h * 4096 + n * 64 + m] = rpb[idx * NHEAD + h];
}

// ---------------------------------------------------------------------------
// Generic tf32 GEMM: C[M,N] = A[M,256] * W[N,256]^T + bias[N]
// Block tile 128x64, BK=32, 256 threads (8 warps in 4(m) x 2(n)), warp 32x32.
// ---------------------------------------------------------------------------
template <int N>
__device__ __forceinline__ void gemm_core(const float* __restrict__ A,
                                          const float* __restrict__ W,
                                          const float* __restrict__ bias,
                                          float* __restrict__ C) {
    constexpr int K = 256;
    __shared__ __align__(16) float As[128][36];
    __shared__ __align__(16) float Bs[64][36];

    const int tid  = threadIdx.x;
    const int lane = tid & 31;
    const int warp = tid >> 5;
    const int wm = warp & 3, wn = warp >> 2;
    const int tg = lane & 3, gp = lane >> 2;
    const long long rowBase = (long long)blockIdx.x * 128;
    const int colBase = blockIdx.y * 64;

    float4 pa[4], pb[2];

    // prefetch kt = 0
    {
        const int kt = 0;
#pragma unroll
        for (int i = 0; i < 4; i++) {
            int f4 = tid + i * 256;
            int r = f4 >> 3, c4 = f4 & 7;
            pa[i] = *(const float4*)(A + (rowBase + r) * K + kt + c4 * 4);
        }
#pragma unroll
        for (int i = 0; i < 2; i++) {
            int f4 = tid + i * 256;
            int r = f4 >> 3, c4 = f4 & 7;
            pb[i] = *(const float4*)(W + (long long)(colBase + r) * K + kt + c4 * 4);
        }
    }

    float acc[2][4][4];
#pragma unroll
    for (int mt = 0; mt < 2; mt++)
#pragma unroll
        for (int nt = 0; nt < 4; nt++)
#pragma unroll
            for (int i = 0; i < 4; i++) acc[mt][nt][i] = 0.0f;

#pragma unroll 1
    for (int kt = 0; kt < K; kt += 32) {
        // stage regs -> smem (with tf32 rounding)
#pragma unroll
        for (int i = 0; i < 4; i++) {
            int f4 = tid + i * 256;
            int r = f4 >> 3, c = (f4 & 7) * 4;
            As[r][c + 0] = tf32r(pa[i].x);
            As[r][c + 1] = tf32r(pa[i].y);
            As[r][c + 2] = tf32r(pa[i].z);
            As[r][c + 3] = tf32r(pa[i].w);
        }
#pragma unroll
        for (int i = 0; i < 2; i++) {
            int f4 = tid + i * 256;
            int r = f4 >> 3, c = (f4 & 7) * 4;
            Bs[r][c + 0] = tf32r(pb[i].x);
            Bs[r][c + 1] = tf32r(pb[i].y);
            Bs[r][c + 2] = tf32r(pb[i].z);
            Bs[r][c + 3] = tf32r(pb[i].w);
        }
        __syncthreads();

        // prefetch next tile while computing
        if (kt + 32 < K) {
            const int ktn = kt + 32;
#pragma unroll
            for (int i = 0; i < 4; i++) {
                int f4 = tid + i * 256;
                int r = f4 >> 3, c4 = f4 & 7;
                pa[i] = *(const float4*)(A + (rowBase + r) * K + ktn + c4 * 4);
            }
#pragma unroll
            for (int i = 0; i < 2; i++) {
                int f4 = tid + i * 256;
                int r = f4 >> 3, c4 = f4 & 7;
                pb[i] = *(const float4*)(W + (long long)(colBase + r) * K + ktn + c4 * 4);
            }
        }

#pragma unroll
        for (int kk = 0; kk < 32; kk += 8) {
            uint32_t a[2][4];
#pragma unroll
            for (int mt = 0; mt < 2; mt++) {
                int r0 = wm * 32 + mt * 16 + gp;
                a[mt][0] = __float_as_uint(As[r0][kk + tg]);
                a[mt][1] = __float_as_uint(As[r0 + 8][kk + tg]);
                a[mt][2] = __float_as_uint(As[r0][kk + tg + 4]);
                a[mt][3] = __float_as_uint(As[r0 + 8][kk + tg + 4]);
            }
#pragma unroll
            for (int nt = 0; nt < 4; nt++) {
                int c0 = wn * 32 + nt * 8 + gp;
                uint32_t b0 = __float_as_uint(Bs[c0][kk + tg]);
                uint32_t b1 = __float_as_uint(Bs[c0][kk + tg + 4]);
#pragma unroll
                for (int mt = 0; mt < 2; mt++)
                    mma_tf32(acc[mt][nt], a[mt], b0, b1);
            }
        }
        __syncthreads();
    }

    // epilogue: bias + store
#pragma unroll
    for (int mt = 0; mt < 2; mt++) {
        long long r0 = rowBase + wm * 32 + mt * 16 + gp;
#pragma unroll
        for (int nt = 0; nt < 4; nt++) {
            int c0 = colBase + wn * 32 + nt * 8 + tg * 2;
            float b0 = __ldg(bias + c0), b1 = __ldg(bias + c0 + 1);
            float2 v01 = make_float2(acc[mt][nt][0] + b0, acc[mt][nt][1] + b1);
            float2 v23 = make_float2(acc[mt][nt][2] + b0, acc[mt][nt][3] + b1);
            *(float2*)(C + r0 * N + c0)       = v01;
            *(float2*)(C + (r0 + 8) * N + c0) = v23;
        }
    }
}

__global__ __launch_bounds__(256, 2) void gemm_q_kernel(const float* __restrict__ A,
                                                        const float* __restrict__ W,
                                                        const float* __restrict__ bias) {
    gemm_core<256>(A, W, bias, g_q);
}
__global__ __launch_bounds__(256, 2) void gemm_kv_kernel(const float* __restrict__ A,
                                                         const float* __restrict__ W,
                                                         const float* __restrict__ bias) {
    gemm_core<512>(A, W, bias, g_kv);
}
__global__ __launch_bounds__(256, 2) void gemm_proj_kernel(const float* __restrict__ W,
                                                           const float* __restrict__ bias,
                                                           float* __restrict__ C) {
    gemm_core<256>(g_att, W, bias, C);
}

// ---------------------------------------------------------------------------
// Fused attention: one block per (b, t, h); 128 threads (4 warps).
// Warp w owns rows [16w, 16w+16). logits mma -> bias+softmax -> P*V mma.
// ---------------------------------------------------------------------------
__global__ __launch_bounds__(128, 4) void attn_kernel() {
    __shared__ __align__(16) float qs[64][36];
    __shared__ __align__(16) float ks[64][36];
    __shared__ __align__(16) float vs[64][36];
    __shared__ __align__(16) float ps[64][68];

    const int bid = blockIdx.x;
    const int h = bid & 7;
    const int t = (bid >> 3) & 1;
    const int b = bid >> 4;
    const int tid = threadIdx.x;
    const int warp = tid >> 5, lane = tid & 31;
    const int tg = lane & 3, gp = lane >> 2;
    const float scale = 0.17677669529663687f;   // 1/sqrt(32)

    const float* qptr = g_q + ((long long)b * NTOK) * CDIM + h * HDIM;
    const float* kptr = g_kv + (((long long)b * T_SZ + t) * NTOK) * (2 * CDIM) + h * HDIM;
    const float* vptr = kptr + CDIM;

    // cooperative load of q, k, v head slices (64 x 32 each) with tf32 rounding
#pragma unroll
    for (int i = 0; i < 4; i++) {
        int f4 = tid + i * 128;
        int r = f4 >> 3, c = (f4 & 7) * 4;
        float4 q4 = *(const float4*)(qptr + (long long)r * CDIM + c);
        qs[r][c + 0] = tf32r(q4.x * scale);
        qs[r][c + 1] = tf32r(q4.y * scale);
        qs[r][c + 2] = tf32r(q4.z * scale);
        qs[r][c + 3] = tf32r(q4.w * scale);
        float4 k4 = *(const float4*)(kptr + (long long)r * (2 * CDIM) + c);
        ks[r][c + 0] = tf32r(k4.x);
        ks[r][c + 1] = tf32r(k4.y);
        ks[r][c + 2] = tf32r(k4.z);
        ks[r][c + 3] = tf32r(k4.w);
        float4 v4 = *(const float4*)(vptr + (long long)r * (2 * CDIM) + c);
        vs[r][c + 0] = tf32r(v4.x);
        vs[r][c + 1] = tf32r(v4.y);
        vs[r][c + 2] = tf32r(v4.z);
        vs[r][c + 3] = tf32r(v4.w);
    }
    __syncthreads();

    // ---- logits: S = (q*scale) @ k^T  (warp computes rows [16w,16w+16)) ----
    float s[8][4];
#pragma unroll
    for (int nt = 0; nt < 8; nt++) {
        s[nt][0] = s[nt][1] = s[nt][2] = s[nt][3] = 0.0f;
    }
    const int row0 = warp * 16;
#pragma unroll
    for (int kk = 0; kk < HDIM; kk += 8) {
        uint32_t a[4];
        a[0] = __float_as_uint(qs[row0 + gp][kk + tg]);
        a[1] = __float_as_uint(qs[row0 + 8 + gp][kk + tg]);
        a[2] = __float_as_uint(qs[row0 + gp][kk + tg + 4]);
        a[3] = __float_as_uint(qs[row0 + 8 + gp][kk + tg + 4]);
#pragma unroll
        for (int nt = 0; nt < 8; nt++) {
            uint32_t b0 = __float_as_uint(ks[nt * 8 + gp][kk + tg]);
            uint32_t b1 = __float_as_uint(ks[nt * 8 + gp][kk + tg + 4]);
            mma_tf32(s[nt], a, b0, b1);
        }
    }

    // ---- bias add + softmax over 64 cols (rows r1=row0+gp, r2=r1+8) ----
    const int r1 = row0 + gp, r2 = r1 + 8;
    const float* bh = g_bias + h * 4096;
    float m1 = -1e30f, m2 = -1e30f;
#pragma unroll
    for (int nt = 0; nt < 8; nt++) {
        int c = nt * 8 + tg * 2;
        s[nt][0] += bh[r1 * 64 + c];
        s[nt][1] += bh[r1 * 64 + c + 1];
        s[nt][2] += bh[r2 * 64 + c];
        s[nt][3] += bh[r2 * 64 + c + 1];
        m1 = fmaxf(m1, fmaxf(s[nt][0], s[nt][1]));
        m2 = fmaxf(m2, fmaxf(s[nt][2], s[nt][3]));
    }
    m1 = fmaxf(m1, __shfl_xor_sync(0xffffffffu, m1, 1));
    m1 = fmaxf(m1, __shfl_xor_sync(0xffffffffu, m1, 2));
    m2 = fmaxf(m2, __shfl_xor_sync(0xffffffffu, m2, 1));
    m2 = fmaxf(m2, __shfl_xor_sync(0xffffffffu, m2, 2));

    float sum1 = 0.0f, sum2 = 0.0f;
#pragma unroll
    for (int nt = 0; nt < 8; nt++) {
        s[nt][0] = __expf(s[nt][0] - m1);
        s[nt][1] = __expf(s[nt][1] - m1);
        s[nt][2] = __expf(s[nt][2] - m2);
        s[nt][3] = __expf(s[nt][3] - m2);
        sum1 += s[nt][0] + s[nt][1];
        sum2 += s[nt][2] + s[nt][3];
    }
    sum1 += __shfl_xor_sync(0xffffffffu, sum1, 1);
    sum1 += __shfl_xor_sync(0xffffffffu, sum1, 2);
    sum2 += __shfl_xor_sync(0xffffffffu, sum2, 1);
    sum2 += __shfl_xor_sync(0xffffffffu, sum2, 2);
    float inv1 = 1.0f / sum1;
    float inv2 = 1.0f / sum2;

#pragma unroll
    for (int nt = 0; nt < 8; nt++) {
        int c = nt * 8 + tg * 2;
        float2 p1 = make_float2(tf32r(s[nt][0] * inv1), tf32r(s[nt][1] * inv1));
        float2 p2 = make_float2(tf32r(s[nt][2] * inv2), tf32r(s[nt][3] * inv2));
        *(float2*)&ps[r1][c] = p1;
        *(float2*)&ps[r2][c] = p2;
    }
    __syncwarp();   // P rows are warp-private; warp-level visibility suffices

    // ---- O = P @ V  (64x64 x 64x32) ----
    float o[4][4];
#pragma unroll
    for (int nt = 0; nt < 4; nt++) {
        o[nt][0] = o[nt][1] = o[nt][2] = o[nt][3] = 0.0f;
    }
#pragma unroll
    for (int kk = 0; kk < NTOK; kk += 8) {
        uint32_t a[4];
        a[0] = __float_as_uint(ps[row0 + gp][kk + tg]);
        a[1] = __float_as_uint(ps[row0 + 8 + gp][kk + tg]);
        a[2] = __float_as_uint(ps[row0 + gp][kk + tg + 4]);
        a[3] = __float_as_uint(ps[row0 + 8 + gp][kk + tg + 4]);
#pragma unroll
        for (int nt = 0; nt < 4; nt++) {
            uint32_t b0 = __float_as_uint(vs[kk + tg][nt * 8 + gp]);
            uint32_t b1 = __float_as_uint(vs[kk + tg + 4][nt * 8 + gp]);
            mma_tf32(o[nt], a, b0, b1);
        }
    }

    // ---- store merged-head output (B*T*N, C) at col h*32 ----
    float* op = g_att + (((long long)b * T_SZ + t) * NTOK) * CDIM + h * HDIM;
#pragma unroll
    for (int nt = 0; nt < 4; nt++) {
        int c = nt * 8 + tg * 2;
        *(float2*)(op + (long long)r1 * CDIM + c) = make_float2(o[nt][0], o[nt][1]);
        *(float2*)(op + (long long)r2 * CDIM + c) = make_float2(o[nt][2], o[nt][3]);
    }
}

// ---------------------------------------------------------------------------
// Launch
// ---------------------------------------------------------------------------
extern "C" void kernel_launch(void* const* d_in, const int* in_sizes, int n_in,
                              void* d_out, int out_size) {
    const float* x      = (const float*)d_in[0];
    const float* memory = (const float*)d_in[1];
    const float* q_w    = (const float*)d_in[2];
    const float* q_b    = (const float*)d_in[3];
    const float* kv_w   = (const float*)d_in[4];
    const float* kv_b   = (const float*)d_in[5];
    const float* proj_w = (const float*)d_in[6];
    const float* proj_b = (const float*)d_in[7];
    const float* rpb    = (const float*)d_in[8];
    float* out = (float*)d_out;

    // (H,64,64) dense bias table (128 KB, L2-resident)
    bias_kernel<<<64, 64>>>(rpb);

    // q projection: (131072 x 256) @ (256 x 256)^T
    gemm_q_kernel<<<dim3(1024, 4), 256>>>(x, q_w, q_b);

    // kv projection: (262144 x 256) @ (512 x 256)^T
    gemm_kv_kernel<<<dim3(2048, 8), 256>>>(memory, kv_w, kv_b);

    // fused attention: one block per (b, t, h)
    attn_kernel<<<B_SZ * T_SZ * NHEAD, 128>>>();

    // output projection: (262144 x 256) @ (256 x 256)^T -> d_out
    gemm_proj_kernel<<<dim3(2048, 4), 256>>>(proj_w, proj_b, out);
}

// round 5
// speedup vs baseline: 1.2029x; 1.2029x over previous
#include <cuda_runtime.h>
#include <cuda_bf16.h>
#include <cstdint>

// ---------------------------------------------------------------------------
// Problem constants: B=2048, T=2, N(tokens)=64, C=256, H=8, hd=32
// ---------------------------------------------------------------------------
#define B_SZ   2048
#define T_SZ   2
#define NTOK   64
#define CDIM   256
#define NHEAD  8
#define HDIM   32

// Scratch (allocation-free contract: __device__ globals)
__device__ float g_q   [33554432];    // (B*N, C)        = 131072 x 256
__device__ float g_kv  [134217728];   // (B*T*N, 2C)     = 262144 x 512
__device__ float g_att [67108864];    // (B*T*N, C)      = 262144 x 256
__device__ float g_bias[32768];       // (H, N, N)       = 8 x 64 x 64

// ---------------------------------------------------------------------------
// Helpers
// ---------------------------------------------------------------------------
__device__ __forceinline__ float tf32r(float x) {
    uint32_t u;
    asm("cvt.rna.tf32.f32 %0, %1;" : "=r"(u) : "f"(x));
    return __uint_as_float(u);
}
__device__ __forceinline__ float4 tf32r4(float4 v) {
    return make_float4(tf32r(v.x), tf32r(v.y), tf32r(v.z), tf32r(v.w));
}

__device__ __forceinline__ void mma_tf32(float (&d)[4], const uint32_t (&a)[4],
                                         uint32_t b0, uint32_t b1) {
    asm volatile(
        "mma.sync.aligned.m16n8k8.row.col.f32.tf32.tf32.f32 "
        "{%0,%1,%2,%3}, {%4,%5,%6,%7}, {%8,%9}, {%0,%1,%2,%3};\n"
        : "+f"(d[0]), "+f"(d[1]), "+f"(d[2]), "+f"(d[3])
        : "r"(a[0]), "r"(a[1]), "r"(a[2]), "r"(a[3]), "r"(b0), "r"(b1));
}

// ---------------------------------------------------------------------------
// Relative position bias table -> dense (H, 64, 64)
// ---------------------------------------------------------------------------
__global__ void bias_kernel(const float* __restrict__ rpb) {
    int n = blockIdx.x;    // 0..63 (query token)
    int m = threadIdx.x;   // 0..63 (key token)
    int in_ = n >> 3, jn = n & 7;
    int im  = m >> 3, jm = m & 7;
    int idx = (in_ - im + 7) * 15 + (jn - jm + 7);
#pragma unroll
    for (int h = 0; h < NHEAD; h++)
        g_bias[h * 4096 + n * 64 + m] = rpb[idx * NHEAD + h];
}

// ---------------------------------------------------------------------------
// tf32 GEMM: C[M,N] = A[M,256] * W[N,256]^T + bias[N]
// Block tile 128x128, BK=32, 256 threads = 8 warps (2m x 4n), warp 64x32.
// Per kk-step: 24 LDS feed 16 MMAs (1.5 issue/MMA).
// ---------------------------------------------------------------------------
template <int N>
__device__ __forceinline__ void gemm_core(const float* __restrict__ A,
                                          const float* __restrict__ W,
                                          const float* __restrict__ bias,
                                          float* __restrict__ C) {
    constexpr int K = 256;
    __shared__ __align__(16) float As[128][36];
    __shared__ __align__(16) float Bs[128][36];

    const int tid  = threadIdx.x;
    const int lane = tid & 31;
    const int warp = tid >> 5;
    const int wm = warp & 1, wn = warp >> 1;       // 2 x 4 warp grid
    const int tg = lane & 3, gp = lane >> 2;
    const long long rowBase = (long long)blockIdx.x * 128;
    const int colBase = blockIdx.y * 128;

    const int ldr = tid >> 3;          // 0..31
    const int ldc = (tid & 7) * 4;     // float4 col within 32-wide k-tile

    float4 pa[4], pb[4];

    // prefetch kt = 0
#pragma unroll
    for (int i = 0; i < 4; i++) {
        int r = ldr + i * 32;
        pa[i] = *(const float4*)(A + (rowBase + r) * K + ldc);
        pb[i] = *(const float4*)(W + (long long)(colBase + r) * K + ldc);
    }

    float acc[4][4][4];
#pragma unroll
    for (int mt = 0; mt < 4; mt++)
#pragma unroll
        for (int nt = 0; nt < 4; nt++)
#pragma unroll
            for (int i = 0; i < 4; i++) acc[mt][nt][i] = 0.0f;

#pragma unroll 1
    for (int kt = 0; kt < K; kt += 32) {
        // stage regs -> smem with tf32 rounding (vectorized)
#pragma unroll
        for (int i = 0; i < 4; i++) {
            int r = ldr + i * 32;
            *(float4*)&As[r][ldc] = tf32r4(pa[i]);
            *(float4*)&Bs[r][ldc] = tf32r4(pb[i]);
        }
        __syncthreads();

        // prefetch next tile while computing
        if (kt + 32 < K) {
            const int ktn = kt + 32;
#pragma unroll
            for (int i = 0; i < 4; i++) {
                int r = ldr + i * 32;
                pa[i] = *(const float4*)(A + (rowBase + r) * K + ktn + ldc);
                pb[i] = *(const float4*)(W + (long long)(colBase + r) * K + ktn + ldc);
            }
        }

#pragma unroll
        for (int kk = 0; kk < 32; kk += 8) {
            uint32_t a[4][4];
#pragma unroll
            for (int mt = 0; mt < 4; mt++) {
                int r0 = wm * 64 + mt * 16 + gp;
                a[mt][0] = __float_as_uint(As[r0][kk + tg]);
                a[mt][1] = __float_as_uint(As[r0 + 8][kk + tg]);
                a[mt][2] = __float_as_uint(As[r0][kk + tg + 4]);
                a[mt][3] = __float_as_uint(As[r0 + 8][kk + tg + 4]);
            }
#pragma unroll
            for (int nt = 0; nt < 4; nt++) {
                int c0 = wn * 32 + nt * 8 + gp;
                uint32_t b0 = __float_as_uint(Bs[c0][kk + tg]);
                uint32_t b1 = __float_as_uint(Bs[c0][kk + tg + 4]);
#pragma unroll
                for (int mt = 0; mt < 4; mt++)
                    mma_tf32(acc[mt][nt], a[mt], b0, b1);
            }
        }
        __syncthreads();
    }

    // epilogue: bias + store
#pragma unroll
    for (int mt = 0; mt < 4; mt++) {
        long long r0 = rowBase + wm * 64 + mt * 16 + gp;
#pragma unroll
        for (int nt = 0; nt < 4; nt++) {
            int c0 = colBase + wn * 32 + nt * 8 + tg * 2;
            float b0 = __ldg(bias + c0), b1 = __ldg(bias + c0 + 1);
            *(float2*)(C + r0 * N + c0) =
                make_float2(acc[mt][nt][0] + b0, acc[mt][nt][1] + b1);
            *(float2*)(C + (r0 + 8) * N + c0) =
                make_float2(acc[mt][nt][2] + b0, acc[mt][nt][3] + b1);
        }
    }
}

__global__ __launch_bounds__(256) void gemm_q_kernel(const float* __restrict__ A,
                                                     const float* __restrict__ W,
                                                     const float* __restrict__ bias) {
    gemm_core<256>(A, W, bias, g_q);
}
__global__ __launch_bounds__(256) void gemm_kv_kernel(const float* __restrict__ A,
                                                      const float* __restrict__ W,
                                                      const float* __restrict__ bias) {
    gemm_core<512>(A, W, bias, g_kv);
}
__global__ __launch_bounds__(256) void gemm_proj_kernel(const float* __restrict__ W,
                                                        const float* __restrict__ bias,
                                                        float* __restrict__ C) {
    gemm_core<256>(g_att, W, bias, C);
}

// ---------------------------------------------------------------------------
// Fused attention: one block per (b, t, h); 64 threads (2 warps).
// Warp w owns rows [32w, 32w+32): 32x64 logits tile, 32x32 output tile.
// P buffer aliases the dead q/k smem after logits.
// ---------------------------------------------------------------------------
#define QS(r, c) sm[(r) * 36 + (c)]
#define KS(r, c) sm[2304 + (r) * 36 + (c)]
#define VS(r, c) sm[4608 + (r) * 36 + (c)]
#define PS(r, c) sm[(r) * 68 + (c)]          // aliases QS/KS region only

__global__ __launch_bounds__(64) void attn_kernel() {
    __shared__ __align__(16) float sm[3 * 64 * 36];

    const int bid = blockIdx.x;
    const int h = bid & 7;
    const int t = (bid >> 3) & 1;
    const int b = bid >> 4;
    const int tid = threadIdx.x;
    const int warp = tid >> 5, lane = tid & 31;
    const int tg = lane & 3, gp = lane >> 2;
    const float scale = 0.17677669529663687f;   // 1/sqrt(32)

    const float* qptr = g_q + ((long long)b * NTOK) * CDIM + h * HDIM;
    const float* kptr = g_kv + (((long long)b * T_SZ + t) * NTOK) * (2 * CDIM) + h * HDIM;
    const float* vptr = kptr + CDIM;

    // cooperative load of q, k, v head slices (64 x 32 each) with tf32 rounding
#pragma unroll
    for (int i = 0; i < 8; i++) {
        int f4 = tid + i * 64;
        int r = f4 >> 3, c = (f4 & 7) * 4;
        float4 q4 = *(const float4*)(qptr + (long long)r * CDIM + c);
        *(float4*)&QS(r, c) = make_float4(tf32r(q4.x * scale), tf32r(q4.y * scale),
                                          tf32r(q4.z * scale), tf32r(q4.w * scale));
        *(float4*)&KS(r, c) = tf32r4(*(const float4*)(kptr + (long long)r * (2 * CDIM) + c));
        *(float4*)&VS(r, c) = tf32r4(*(const float4*)(vptr + (long long)r * (2 * CDIM) + c));
    }
    __syncthreads();

    // ---- logits: S = (q*scale) @ k^T ; warp tile 32x64 ----
    float s[2][8][4];
#pragma unroll
    for (int mt = 0; mt < 2; mt++)
#pragma unroll
        for (int nt = 0; nt < 8; nt++)
            s[mt][nt][0] = s[mt][nt][1] = s[mt][nt][2] = s[mt][nt][3] = 0.0f;

    const int row0 = warp * 32;
#pragma unroll
    for (int kk = 0; kk < HDIM; kk += 8) {
        uint32_t a[2][4];
#pragma unroll
        for (int mt = 0; mt < 2; mt++) {
            int r0 = row0 + mt * 16 + gp;
            a[mt][0] = __float_as_uint(QS(r0, kk + tg));
            a[mt][1] = __float_as_uint(QS(r0 + 8, kk + tg));
            a[mt][2] = __float_as_uint(QS(r0, kk + tg + 4));
            a[mt][3] = __float_as_uint(QS(r0 + 8, kk + tg + 4));
        }
#pragma unroll
        for (int nt = 0; nt < 8; nt++) {
            uint32_t b0 = __float_as_uint(KS(nt * 8 + gp, kk + tg));
            uint32_t b1 = __float_as_uint(KS(nt * 8 + gp, kk + tg + 4));
#pragma unroll
            for (int mt = 0; mt < 2; mt++)
                mma_tf32(s[mt][nt], a[mt], b0, b1);
        }
    }

    // ---- bias add + softmax (4 rows per thread: mt x {gp, gp+8}) ----
    const float* bh = g_bias + h * 4096;
    float inv[2][2];
#pragma unroll
    for (int mt = 0; mt < 2; mt++) {
        const int r1 = row0 + mt * 16 + gp, r2 = r1 + 8;
        float m1 = -1e30f, m2 = -1e30f;
#pragma unroll
        for (int nt = 0; nt < 8; nt++) {
            int c = nt * 8 + tg * 2;
            float2 bb1 = *(const float2*)(bh + r1 * 64 + c);
            float2 bb2 = *(const float2*)(bh + r2 * 64 + c);
            s[mt][nt][0] += bb1.x;  s[mt][nt][1] += bb1.y;
            s[mt][nt][2] += bb2.x;  s[mt][nt][3] += bb2.y;
            m1 = fmaxf(m1, fmaxf(s[mt][nt][0], s[mt][nt][1]));
            m2 = fmaxf(m2, fmaxf(s[mt][nt][2], s[mt][nt][3]));
        }
        m1 = fmaxf(m1, __shfl_xor_sync(0xffffffffu, m1, 1));
        m1 = fmaxf(m1, __shfl_xor_sync(0xffffffffu, m1, 2));
        m2 = fmaxf(m2, __shfl_xor_sync(0xffffffffu, m2, 1));
        m2 = fmaxf(m2, __shfl_xor_sync(0xffffffffu, m2, 2));

        float sum1 = 0.0f, sum2 = 0.0f;
#pragma unroll
        for (int nt = 0; nt < 8; nt++) {
            s[mt][nt][0] = __expf(s[mt][nt][0] - m1);
            s[mt][nt][1] = __expf(s[mt][nt][1] - m1);
            s[mt][nt][2] = __expf(s[mt][nt][2] - m2);
            s[mt][nt][3] = __expf(s[mt][nt][3] - m2);
            sum1 += s[mt][nt][0] + s[mt][nt][1];
            sum2 += s[mt][nt][2] + s[mt][nt][3];
        }
        sum1 += __shfl_xor_sync(0xffffffffu, sum1, 1);
        sum1 += __shfl_xor_sync(0xffffffffu, sum1, 2);
        sum2 += __shfl_xor_sync(0xffffffffu, sum2, 1);
        sum2 += __shfl_xor_sync(0xffffffffu, sum2, 2);
        inv[mt][0] = 1.0f / sum1;
        inv[mt][1] = 1.0f / sum2;
    }

    // q/k smem is dead now; P aliases it. Both warps must be done reading.
    __syncthreads();
#pragma unroll
    for (int mt = 0; mt < 2; mt++) {
        const int r1 = row0 + mt * 16 + gp, r2 = r1 + 8;
#pragma unroll
        for (int nt = 0; nt < 8; nt++) {
            int c = nt * 8 + tg * 2;
            *(float2*)&PS(r1, c) = make_float2(tf32r(s[mt][nt][0] * inv[mt][0]),
                                               tf32r(s[mt][nt][1] * inv[mt][0]));
            *(float2*)&PS(r2, c) = make_float2(tf32r(s[mt][nt][2] * inv[mt][1]),
                                               tf32r(s[mt][nt][3] * inv[mt][1]));
        }
    }
    __syncwarp();   // P rows are warp-private; warp-level visibility suffices

    // ---- O = P @ V  (warp: 32x64 @ 64x32) ----
    float o[2][4][4];
#pragma unroll
    for (int mt = 0; mt < 2; mt++)
#pragma unroll
        for (int nt = 0; nt < 4; nt++)
            o[mt][nt][0] = o[mt][nt][1] = o[mt][nt][2] = o[mt][nt][3] = 0.0f;

#pragma unroll
    for (int kk = 0; kk < NTOK; kk += 8) {
        uint32_t a[2][4];
#pragma unroll
        for (int mt = 0; mt < 2; mt++) {
            int r0 = row0 + mt * 16 + gp;
            a[mt][0] = __float_as_uint(PS(r0, kk + tg));
            a[mt][1] = __float_as_uint(PS(r0 + 8, kk + tg));
            a[mt][2] = __float_as_uint(PS(r0, kk + tg + 4));
            a[mt][3] = __float_as_uint(PS(r0 + 8, kk + tg + 4));
        }
#pragma unroll
        for (int nt = 0; nt < 4; nt++) {
            uint32_t b0 = __float_as_uint(VS(kk + tg, nt * 8 + gp));
            uint32_t b1 = __float_as_uint(VS(kk + tg + 4, nt * 8 + gp));
#pragma unroll
            for (int mt = 0; mt < 2; mt++)
                mma_tf32(o[mt][nt], a[mt], b0, b1);
        }
    }

    // ---- store merged-head output (B*T*N, C) at col h*32 ----
    float* op = g_att + (((long long)b * T_SZ + t) * NTOK) * CDIM + h * HDIM;
#pragma unroll
    for (int mt = 0; mt < 2; mt++) {
        const int r1 = row0 + mt * 16 + gp, r2 = r1 + 8;
#pragma unroll
        for (int nt = 0; nt < 4; nt++) {
            int c = nt * 8 + tg * 2;
            *(float2*)(op + (long long)r1 * CDIM + c) = make_float2(o[mt][nt][0], o[mt][nt][1]);
            *(float2*)(op + (long long)r2 * CDIM + c) = make_float2(o[mt][nt][2], o[mt][nt][3]);
        }
    }
}

// ---------------------------------------------------------------------------
// Launch
// ---------------------------------------------------------------------------
extern "C" void kernel_launch(void* const* d_in, const int* in_sizes, int n_in,
                              void* d_out, int out_size) {
    const float* x      = (const float*)d_in[0];
    const float* memory = (const float*)d_in[1];
    const float* q_w    = (const float*)d_in[2];
    const float* q_b    = (const float*)d_in[3];
    const float* kv_w   = (const float*)d_in[4];
    const float* kv_b   = (const float*)d_in[5];
    const float* proj_w = (const float*)d_in[6];
    const float* proj_b = (const float*)d_in[7];
    const float* rpb    = (const float*)d_in[8];
    float* out = (float*)d_out;

    // (H,64,64) dense bias table (128 KB, L2-resident)
    bias_kernel<<<64, 64>>>(rpb);

    // q projection: (131072 x 256) @ (256 x 256)^T
    gemm_q_kernel<<<dim3(1024, 2), 256>>>(x, q_w, q_b);

    // kv projection: (262144 x 256) @ (512 x 256)^T
    gemm_kv_kernel<<<dim3(2048, 4), 256>>>(memory, kv_w, kv_b);

    // fused attention: one block per (b, t, h), 2 warps
    attn_kernel<<<B_SZ * T_SZ * NHEAD, 64>>>();

    // output projection: (262144 x 256) @ (256 x 256)^T -> d_out
    gemm_proj_kernel<<<dim3(2048, 2), 256>>>(proj_w, proj_b, out);
}

// round 9
// speedup vs baseline: 1.5594x; 1.2964x over previous
#include <cuda_runtime.h>
#include <cuda_fp16.h>
#include <cstdint>

// ---------------------------------------------------------------------------
// Problem constants: B=2048, T=2, N(tokens)=64, C=256, H=8, hd=32
// ---------------------------------------------------------------------------
#define B_SZ   2048
#define T_SZ   2
#define NTOK   64
#define CDIM   256
#define NHEAD  8
#define HDIM   32

// Scratch (allocation-free contract: __device__ globals)
__device__ float g_q   [33554432];    // (B*N, C)        = 131072 x 256
__device__ float g_kv  [134217728];   // (B*T*N, 2C)     = 262144 x 512
__device__ float g_att [67108864];    // (B*T*N, C)      = 262144 x 256
__device__ float g_bias[32768];       // (H, N, N)       = 8 x 64 x 64

// ---------------------------------------------------------------------------
// Helpers
// ---------------------------------------------------------------------------
__device__ __forceinline__ void mma_f16(float (&d)[4], const uint32_t (&a)[4],
                                        uint32_t b0, uint32_t b1) {
    asm volatile(
        "mma.sync.aligned.m16n8k16.row.col.f32.f16.f16.f32 "
        "{%0,%1,%2,%3}, {%4,%5,%6,%7}, {%8,%9}, {%0,%1,%2,%3};\n"
        : "+f"(d[0]), "+f"(d[1]), "+f"(d[2]), "+f"(d[3])
        : "r"(a[0]), "r"(a[1]), "r"(a[2]), "r"(a[3]), "r"(b0), "r"(b1));
}

__device__ __forceinline__ uint2 h4pack(float4 v) {
    __half2 lo = __floats2half2_rn(v.x, v.y);
    __half2 hi = __floats2half2_rn(v.z, v.w);
    uint2 u;
    u.x = *reinterpret_cast<uint32_t*>(&lo);
    u.y = *reinterpret_cast<uint32_t*>(&hi);
    return u;
}

// ---------------------------------------------------------------------------
// Relative position bias table -> dense (H, 64, 64)
// ---------------------------------------------------------------------------
__global__ void bias_kernel(const float* __restrict__ rpb) {
    int n = blockIdx.x;    // query token
    int m = threadIdx.x;   // key token
    int in_ = n >> 3, jn = n & 7;
    int im  = m >> 3, jm = m & 7;
    int idx = (in_ - im + 7) * 15 + (jn - jm + 7);
#pragma unroll
    for (int h = 0; h < NHEAD; h++)
        g_bias[h * 4096 + n * 64 + m] = rpb[idx * NHEAD + h];
}

// ---------------------------------------------------------------------------
// fp16 GEMM: C[M,N] = A[M,256] * W[N,256]^T + bias[N]
// Block tile 128x128, BK=32, 256 threads = 8 warps (2m x 4n), warp 64x32.
// mma m16n8k16: per k16-step per warp 24 LDS feed 16 MMAs; 2 steps per tile.
// ---------------------------------------------------------------------------
template <int N>
__device__ __forceinline__ void gemm_core(const float* __restrict__ A,
                                          const float* __restrict__ W,
                                          const float* __restrict__ bias,
                                          float* __restrict__ C) {
    constexpr int K = 256;
    __shared__ __align__(16) __half As[128][40];   // 32 k + 8 pad
    __shared__ __align__(16) __half Bs[128][40];

    const int tid  = threadIdx.x;
    const int lane = tid & 31;
    const int warp = tid >> 5;
    const int wm = warp & 1, wn = warp >> 1;       // 2 x 4 warp grid
    const int tg = lane & 3, gp = lane >> 2;
    const long long rowBase = (long long)blockIdx.x * 128;
    const int colBase = blockIdx.y * 128;

    const int ldr = tid >> 3;          // 0..31
    const int ldc = (tid & 7) * 4;     // float4 col within 32-wide k-tile

    float4 pa[4], pb[4];

    // prefetch kt = 0
#pragma unroll
    for (int i = 0; i < 4; i++) {
        int r = ldr + i * 32;
        pa[i] = *(const float4*)(A + (rowBase + r) * K + ldc);
        pb[i] = *(const float4*)(W + (long long)(colBase + r) * K + ldc);
    }

    float acc[4][4][4];
#pragma unroll
    for (int mt = 0; mt < 4; mt++)
#pragma unroll
        for (int nt = 0; nt < 4; nt++)
#pragma unroll
            for (int i = 0; i < 4; i++) acc[mt][nt][i] = 0.0f;

#pragma unroll 1
    for (int kt = 0; kt < K; kt += 32) {
        // stage regs -> smem as fp16 (RN)
#pragma unroll
        for (int i = 0; i < 4; i++) {
            int r = ldr + i * 32;
            *(uint2*)&As[r][ldc] = h4pack(pa[i]);
            *(uint2*)&Bs[r][ldc] = h4pack(pb[i]);
        }
        __syncthreads();

        // prefetch next tile while computing
        if (kt + 32 < K) {
            const int ktn = kt + 32;
#pragma unroll
            for (int i = 0; i < 4; i++) {
                int r = ldr + i * 32;
                pa[i] = *(const float4*)(A + (rowBase + r) * K + ktn + ldc);
                pb[i] = *(const float4*)(W + (long long)(colBase + r) * K + ktn + ldc);
            }
        }

#pragma unroll
        for (int kk = 0; kk < 32; kk += 16) {
            uint32_t a[4][4];
#pragma unroll
            for (int mt = 0; mt < 4; mt++) {
                int r0 = wm * 64 + mt * 16 + gp;
                a[mt][0] = *(const uint32_t*)&As[r0][kk + tg * 2];
                a[mt][1] = *(const uint32_t*)&As[r0 + 8][kk + tg * 2];
                a[mt][2] = *(const uint32_t*)&As[r0][kk + tg * 2 + 8];
                a[mt][3] = *(const uint32_t*)&As[r0 + 8][kk + tg * 2 + 8];
            }
#pragma unroll
            for (int nt = 0; nt < 4; nt++) {
                int c0 = wn * 32 + nt * 8 + gp;
                uint32_t b0 = *(const uint32_t*)&Bs[c0][kk + tg * 2];
                uint32_t b1 = *(const uint32_t*)&Bs[c0][kk + tg * 2 + 8];
#pragma unroll
                for (int mt = 0; mt < 4; mt++)
                    mma_f16(acc[mt][nt], a[mt], b0, b1);
            }
        }
        __syncthreads();
    }

    // epilogue: bias + store
#pragma unroll
    for (int mt = 0; mt < 4; mt++) {
        long long r0 = rowBase + wm * 64 + mt * 16 + gp;
#pragma unroll
        for (int nt = 0; nt < 4; nt++) {
            int c0 = colBase + wn * 32 + nt * 8 + tg * 2;
            float b0 = __ldg(bias + c0), b1 = __ldg(bias + c0 + 1);
            *(float2*)(C + r0 * N + c0) =
                make_float2(acc[mt][nt][0] + b0, acc[mt][nt][1] + b1);
            *(float2*)(C + (r0 + 8) * N + c0) =
                make_float2(acc[mt][nt][2] + b0, acc[mt][nt][3] + b1);
        }
    }
}

__global__ __launch_bounds__(256) void gemm_q_kernel(const float* __restrict__ A,
                                                     const float* __restrict__ W,
                                                     const float* __restrict__ bias) {
    gemm_core<256>(A, W, bias, g_q);
}
__global__ __launch_bounds__(256) void gemm_kv_kernel(const float* __restrict__ A,
                                                      const float* __restrict__ W,
                                                      const float* __restrict__ bias) {
    gemm_core<512>(A, W, bias, g_kv);
}
__global__ __launch_bounds__(256) void gemm_proj_kernel(const float* __restrict__ W,
                                                        const float* __restrict__ bias,
                                                        float* __restrict__ C) {
    gemm_core<256>(g_att, W, bias, C);
}

// ---------------------------------------------------------------------------
// Fused attention: one block per (b, t, h); 64 threads (2 warps), fp16 MMA.
// Warp w owns rows [32w, 32w+32): 32x64 logits tile, 32x32 output tile.
// smem (halves): QS 64x40, KS 64x40, Vt 32x72 (V transposed: [n][k]).
// P (64x72) aliases the dead QS/KS region after logits.
// ---------------------------------------------------------------------------
#define QS(r, c) smh[(r) * 40 + (c)]
#define KS(r, c) smh[2560 + (r) * 40 + (c)]
#define VT(n, k) smh[5120 + (n) * 72 + (k)]
#define PSH(r, c) smh[(r) * 72 + (c)]        // aliases QS/KS (4608 <= 5120 halves)

__global__ __launch_bounds__(64) void attn_kernel() {
    __shared__ __align__(16) __half smh[2560 * 2 + 32 * 72];

    const int bid = blockIdx.x;
    const int h = bid & 7;
    const int t = (bid >> 3) & 1;
    const int b = bid >> 4;
    const int tid = threadIdx.x;
    const int warp = tid >> 5, lane = tid & 31;
    const int tg = lane & 3, gp = lane >> 2;
    const float scale = 0.17677669529663687f;   // 1/sqrt(32)

    const float* qptr = g_q + ((long long)b * NTOK) * CDIM + h * HDIM;
    const float* kptr = g_kv + (((long long)b * T_SZ + t) * NTOK) * (2 * CDIM) + h * HDIM;
    const float* vptr = kptr + CDIM;

    // cooperative load of q, k (row-major) and v (transposed) as fp16
#pragma unroll
    for (int i = 0; i < 8; i++) {
        int f4 = tid + i * 64;
        int r = f4 >> 3, c = (f4 & 7) * 4;
        float4 q4 = *(const float4*)(qptr + (long long)r * CDIM + c);
        q4.x *= scale; q4.y *= scale; q4.z *= scale; q4.w *= scale;
        *(uint2*)&QS(r, c) = h4pack(q4);
        float4 k4 = *(const float4*)(kptr + (long long)r * (2 * CDIM) + c);
        *(uint2*)&KS(r, c) = h4pack(k4);
        float4 v4 = *(const float4*)(vptr + (long long)r * (2 * CDIM) + c);
        VT(c + 0, r) = __float2half_rn(v4.x);
        VT(c + 1, r) = __float2half_rn(v4.y);
        VT(c + 2, r) = __float2half_rn(v4.z);
        VT(c + 3, r) = __float2half_rn(v4.w);
    }
    __syncthreads();

    // ---- logits: S = (q*scale) @ k^T ; warp tile 32x64, k16 x 2 steps ----
    float s[2][8][4];
#pragma unroll
    for (int mt = 0; mt < 2; mt++)
#pragma unroll
        for (int nt = 0; nt < 8; nt++)
            s[mt][nt][0] = s[mt][nt][1] = s[mt][nt][2] = s[mt][nt][3] = 0.0f;

    const int row0 = warp * 32;
#pragma unroll
    for (int kk = 0; kk < HDIM; kk += 16) {
        uint32_t a[2][4];
#pragma unroll
        for (int mt = 0; mt < 2; mt++) {
            int r0 = row0 + mt * 16 + gp;
            a[mt][0] = *(const uint32_t*)&QS(r0, kk + tg * 2);
            a[mt][1] = *(const uint32_t*)&QS(r0 + 8, kk + tg * 2);
            a[mt][2] = *(const uint32_t*)&QS(r0, kk + tg * 2 + 8);
            a[mt][3] = *(const uint32_t*)&QS(r0 + 8, kk + tg * 2 + 8);
        }
#pragma unroll
        for (int nt = 0; nt < 8; nt++) {
            int m0 = nt * 8 + gp;
            uint32_t b0 = *(const uint32_t*)&KS(m0, kk + tg * 2);
            uint32_t b1 = *(const uint32_t*)&KS(m0, kk + tg * 2 + 8);
#pragma unroll
            for (int mt = 0; mt < 2; mt++)
                mma_f16(s[mt][nt], a[mt], b0, b1);
        }
    }

    // ---- bias add + softmax (4 rows per thread: mt x {gp, gp+8}), fp32 ----
    const float* bh = g_bias + h * 4096;
    float inv[2][2];
#pragma unroll
    for (int mt = 0; mt < 2; mt++) {
        const int r1 = row0 + mt * 16 + gp, r2 = r1 + 8;
        float m1 = -1e30f, m2 = -1e30f;
#pragma unroll
        for (int nt = 0; nt < 8; nt++) {
            int c = nt * 8 + tg * 2;
            float2 bb1 = *(const float2*)(bh + r1 * 64 + c);
            float2 bb2 = *(const float2*)(bh + r2 * 64 + c);
            s[mt][nt][0] += bb1.x;  s[mt][nt][1] += bb1.y;
            s[mt][nt][2] += bb2.x;  s[mt][nt][3] += bb2.y;
            m1 = fmaxf(m1, fmaxf(s[mt][nt][0], s[mt][nt][1]));
            m2 = fmaxf(m2, fmaxf(s[mt][nt][2], s[mt][nt][3]));
        }
        m1 = fmaxf(m1, __shfl_xor_sync(0xffffffffu, m1, 1));
        m1 = fmaxf(m1, __shfl_xor_sync(0xffffffffu, m1, 2));
        m2 = fmaxf(m2, __shfl_xor_sync(0xffffffffu, m2, 1));
        m2 = fmaxf(m2, __shfl_xor_sync(0xffffffffu, m2, 2));

        float sum1 = 0.0f, sum2 = 0.0f;
#pragma unroll
        for (int nt = 0; nt < 8; nt++) {
            s[mt][nt][0] = __expf(s[mt][nt][0] - m1);
            s[mt][nt][1] = __expf(s[mt][nt][1] - m1);
            s[mt][nt][2] = __expf(s[mt][nt][2] - m2);
            s[mt][nt][3] = __expf(s[mt][nt][3] - m2);
            sum1 += s[mt][nt][0] + s[mt][nt][1];
            sum2 += s[mt][nt][2] + s[mt][nt][3];
        }
        sum1 += __shfl_xor_sync(0xffffffffu, sum1, 1);
        sum1 += __shfl_xor_sync(0xffffffffu, sum1, 2);
        sum2 += __shfl_xor_sync(0xffffffffu, sum2, 1);
        sum2 += __shfl_xor_sync(0xffffffffu, sum2, 2);
        inv[mt][0] = 1.0f / sum1;
        inv[mt][1] = 1.0f / sum2;
    }

    // QS/KS are dead; P aliases them. Both warps must be past their reads.
    __syncthreads();
#pragma unroll
    for (int mt = 0; mt < 2; mt++) {
        const int r1 = row0 + mt * 16 + gp, r2 = r1 + 8;
#pragma unroll
        for (int nt = 0; nt < 8; nt++) {
            int c = nt * 8 + tg * 2;
            __half2 p1 = __floats2half2_rn(s[mt][nt][0] * inv[mt][0],
                                           s[mt][nt][1] * inv[mt][0]);
            __half2 p2 = __floats2half2_rn(s[mt][nt][2] * inv[mt][1],
                                           s[mt][nt][3] * inv[mt][1]);
            *(uint32_t*)&PSH(r1, c) = *reinterpret_cast<uint32_t*>(&p1);
            *(uint32_t*)&PSH(r2, c) = *reinterpret_cast<uint32_t*>(&p2);
        }
    }
    __syncwarp();   // P rows are warp-private; warp visibility suffices

    // ---- O = P @ V  (warp: 32x64 @ 64x32), k16 x 4 steps ----
    float o[2][4][4];
#pragma unroll
    for (int mt = 0; mt < 2; mt++)
#pragma unroll
        for (int nt = 0; nt < 4; nt++)
            o[mt][nt][0] = o[mt][nt][1] = o[mt][nt][2] = o[mt][nt][3] = 0.0f;

#pragma unroll
    for (int kk = 0; kk < NTOK; kk += 16) {
        uint32_t a[2][4];
#pragma unroll
        for (int mt = 0; mt < 2; mt++) {
            int r0 = row0 + mt * 16 + gp;
            a[mt][0] = *(const uint32_t*)&PSH(r0, kk + tg * 2);
            a[mt][1] = *(const uint32_t*)&PSH(r0 + 8, kk + tg * 2);
            a[mt][2] = *(const uint32_t*)&PSH(r0, kk + tg * 2 + 8);
            a[mt][3] = *(const uint32_t*)&PSH(r0 + 8, kk + tg * 2 + 8);
        }
#pragma unroll
        for (int nt = 0; nt < 4; nt++) {
            int n0 = nt * 8 + gp;
            uint32_t b0 = *(const uint32_t*)&VT(n0, kk + tg * 2);
            uint32_t b1 = *(const uint32_t*)&VT(n0, kk + tg * 2 + 8);
#pragma unroll
            for (int mt = 0; mt < 2; mt++)
                mma_f16(o[mt][nt], a[mt], b0, b1);
        }
    }

    // ---- store merged-head output (B*T*N, C) at col h*32 ----
    float* op = g_att + (((long long)b * T_SZ + t) * NTOK) * CDIM + h * HDIM;
#pragma unroll
    for (int mt = 0; mt < 2; mt++) {
        const int r1 = row0 + mt * 16 + gp, r2 = r1 + 8;
#pragma unroll
        for (int nt = 0; nt < 4; nt++) {
            int c = nt * 8 + tg * 2;
            *(float2*)(op + (long long)r1 * CDIM + c) = make_float2(o[mt][nt][0], o[mt][nt][1]);
            *(float2*)(op + (long long)r2 * CDIM + c) = make_float2(o[mt][nt][2], o[mt][nt][3]);
        }
    }
}

// ---------------------------------------------------------------------------
// Launch
// ---------------------------------------------------------------------------
extern "C" void kernel_launch(void* const* d_in, const int* in_sizes, int n_in,
                              void* d_out, int out_size) {
    const float* x      = (const float*)d_in[0];
    const float* memory = (const float*)d_in[1];
    const float* q_w    = (const float*)d_in[2];
    const float* q_b    = (const float*)d_in[3];
    const float* kv_w   = (const float*)d_in[4];
    const float* kv_b   = (const float*)d_in[5];
    const float* proj_w = (const float*)d_in[6];
    const float* proj_b = (const float*)d_in[7];
    const float* rpb    = (const float*)d_in[8];
    float* out = (float*)d_out;

    // (H,64,64) dense bias table (128 KB, L2-resident)
    bias_kernel<<<64, 64>>>(rpb);

    // q projection: (131072 x 256) @ (256 x 256)^T
    gemm_q_kernel<<<dim3(1024, 2), 256>>>(x, q_w, q_b);

    // kv projection: (262144 x 256) @ (512 x 256)^T
    gemm_kv_kernel<<<dim3(2048, 4), 256>>>(memory, kv_w, kv_b);

    // fused attention: one block per (b, t, h), 2 warps
    attn_kernel<<<B_SZ * T_SZ * NHEAD, 64>>>();

    // output projection: (262144 x 256) @ (256 x 256)^T -> d_out
    gemm_proj_kernel<<<dim3(2048, 2), 256>>>(proj_w, proj_b, out);
}

// round 14
// speedup vs baseline: 1.6465x; 1.0558x over previous
#include <cuda_runtime.h>
#include <cuda_fp16.h>
#include <cstdint>

// ---------------------------------------------------------------------------
// Problem constants: B=2048, T=2, N(tokens)=64, C=256, H=8, hd=32
// ---------------------------------------------------------------------------
#define B_SZ   2048
#define T_SZ   2
#define NTOK   64
#define CDIM   256
#define NHEAD  8
#define HDIM   32

#define QK_SCALE 0.17677669529663687f   // 1/sqrt(32)

// Scratch (allocation-free contract: __device__ globals) — all fp16 now
__device__ __half g_qh  [33554432];   // (B*N, C)     q projection * scale
__device__ __half g_kvh [134217728];  // (B*T*N, 2C)  kv projection
__device__ __half g_atth[67108864];   // (B*T*N, C)   attention output
__device__ float  g_bias[32768];      // (H, N, N)

// ---------------------------------------------------------------------------
// Helpers
// ---------------------------------------------------------------------------
__device__ __forceinline__ void mma_f16(float (&d)[4], const uint32_t (&a)[4],
                                        uint32_t b0, uint32_t b1) {
    asm volatile(
        "mma.sync.aligned.m16n8k16.row.col.f32.f16.f16.f32 "
        "{%0,%1,%2,%3}, {%4,%5,%6,%7}, {%8,%9}, {%0,%1,%2,%3};\n"
        : "+f"(d[0]), "+f"(d[1]), "+f"(d[2]), "+f"(d[3])
        : "r"(a[0]), "r"(a[1]), "r"(a[2]), "r"(a[3]), "r"(b0), "r"(b1));
}

__device__ __forceinline__ uint2 h4pack(float4 v) {
    __half2 lo = __floats2half2_rn(v.x, v.y);
    __half2 hi = __floats2half2_rn(v.z, v.w);
    uint2 u;
    u.x = *reinterpret_cast<uint32_t*>(&lo);
    u.y = *reinterpret_cast<uint32_t*>(&hi);
    return u;
}

__device__ __forceinline__ uint32_t h2bits(float a, float b) {
    __half2 h = __floats2half2_rn(a, b);
    return *reinterpret_cast<uint32_t*>(&h);
}

// ---------------------------------------------------------------------------
// Relative position bias table -> dense (H, 64, 64)
// ---------------------------------------------------------------------------
__global__ void bias_kernel(const float* __restrict__ rpb) {
    int n = blockIdx.x;    // query token
    int m = threadIdx.x;   // key token
    int in_ = n >> 3, jn = n & 7;
    int im  = m >> 3, jm = m & 7;
    int idx = (in_ - im + 7) * 15 + (jn - jm + 7);
#pragma unroll
    for (int h = 0; h < NHEAD; h++)
        g_bias[h * 4096 + n * 64 + m] = rpb[idx * NHEAD + h];
}

// ---------------------------------------------------------------------------
// fp16 GEMM: C[M,N] = (A[M,256] * W[N,256]^T + bias[N]) * outScale
// A may be fp32 (converted while staging) or fp16 (direct). Output fp16/fp32.
// Block tile 128x128, BK=32, 256 threads = 8 warps (2m x 4n), warp 64x32.
// ---------------------------------------------------------------------------
template <int N, bool AHALF, bool OHALF>
__device__ __forceinline__ void gemm_core(const void* __restrict__ Av,
                                          const float* __restrict__ W,
                                          const float* __restrict__ bias,
                                          void* __restrict__ Cv,
                                          float outScale) {
    constexpr int K = 256;
    __shared__ __align__(16) __half As[128][40];   // 32 k + 8 pad
    __shared__ __align__(16) __half Bs[128][40];

    const float*  Af = (const float*)Av;
    const __half* Ah = (const __half*)Av;

    const int tid  = threadIdx.x;
    const int lane = tid & 31;
    const int warp = tid >> 5;
    const int wm = warp & 1, wn = warp >> 1;       // 2 x 4 warp grid
    const int tg = lane & 3, gp = lane >> 2;
    const long long rowBase = (long long)blockIdx.x * 128;
    const int colBase = blockIdx.y * 128;

    const int ldr = tid >> 3;          // 0..31
    const int ldc = (tid & 7) * 4;     // 4-element col within 32-wide k-tile

    float4 paf[4];
    uint2  pah[4];
    float4 pb[4];

    // prefetch kt = 0
#pragma unroll
    for (int i = 0; i < 4; i++) {
        int r = ldr + i * 32;
        if (AHALF) pah[i] = *(const uint2*)(Ah + (rowBase + r) * K + ldc);
        else       paf[i] = *(const float4*)(Af + (rowBase + r) * K + ldc);
        pb[i] = *(const float4*)(W + (long long)(colBase + r) * K + ldc);
    }

    float acc[4][4][4];
#pragma unroll
    for (int mt = 0; mt < 4; mt++)
#pragma unroll
        for (int nt = 0; nt < 4; nt++)
#pragma unroll
            for (int i = 0; i < 4; i++) acc[mt][nt][i] = 0.0f;

#pragma unroll 1
    for (int kt = 0; kt < K; kt += 32) {
        // stage -> smem as fp16
#pragma unroll
        for (int i = 0; i < 4; i++) {
            int r = ldr + i * 32;
            *(uint2*)&As[r][ldc] = AHALF ? pah[i] : h4pack(paf[i]);
            *(uint2*)&Bs[r][ldc] = h4pack(pb[i]);
        }
        __syncthreads();

        // prefetch next tile while computing
        if (kt + 32 < K) {
            const int ktn = kt + 32;
#pragma unroll
            for (int i = 0; i < 4; i++) {
                int r = ldr + i * 32;
                if (AHALF) pah[i] = *(const uint2*)(Ah + (rowBase + r) * K + ktn + ldc);
                else       paf[i] = *(const float4*)(Af + (rowBase + r) * K + ktn + ldc);
                pb[i] = *(const float4*)(W + (long long)(colBase + r) * K + ktn + ldc);
            }
        }

#pragma unroll
        for (int kk = 0; kk < 32; kk += 16) {
            uint32_t a[4][4];
#pragma unroll
            for (int mt = 0; mt < 4; mt++) {
                int r0 = wm * 64 + mt * 16 + gp;
                a[mt][0] = *(const uint32_t*)&As[r0][kk + tg * 2];
                a[mt][1] = *(const uint32_t*)&As[r0 + 8][kk + tg * 2];
                a[mt][2] = *(const uint32_t*)&As[r0][kk + tg * 2 + 8];
                a[mt][3] = *(const uint32_t*)&As[r0 + 8][kk + tg * 2 + 8];
            }
#pragma unroll
            for (int nt = 0; nt < 4; nt++) {
                int c0 = wn * 32 + nt * 8 + gp;
                uint32_t b0 = *(const uint32_t*)&Bs[c0][kk + tg * 2];
                uint32_t b1 = *(const uint32_t*)&Bs[c0][kk + tg * 2 + 8];
#pragma unroll
                for (int mt = 0; mt < 4; mt++)
                    mma_f16(acc[mt][nt], a[mt], b0, b1);
            }
        }
        __syncthreads();
    }

    // epilogue: bias (+scale) + store
#pragma unroll
    for (int mt = 0; mt < 4; mt++) {
        long long r0 = rowBase + wm * 64 + mt * 16 + gp;
#pragma unroll
        for (int nt = 0; nt < 4; nt++) {
            int c0 = colBase + wn * 32 + nt * 8 + tg * 2;
            float b0 = __ldg(bias + c0), b1 = __ldg(bias + c0 + 1);
            float v0 = (acc[mt][nt][0] + b0) * outScale;
            float v1 = (acc[mt][nt][1] + b1) * outScale;
            float v2 = (acc[mt][nt][2] + b0) * outScale;
            float v3 = (acc[mt][nt][3] + b1) * outScale;
            if (OHALF) {
                __half* C = (__half*)Cv;
                *(uint32_t*)(C + r0 * N + c0)       = h2bits(v0, v1);
                *(uint32_t*)(C + (r0 + 8) * N + c0) = h2bits(v2, v3);
            } else {
                float* C = (float*)Cv;
                *(float2*)(C + r0 * N + c0)       = make_float2(v0, v1);
                *(float2*)(C + (r0 + 8) * N + c0) = make_float2(v2, v3);
            }
        }
    }
}

__global__ __launch_bounds__(256) void gemm_q_kernel(const float* __restrict__ A,
                                                     const float* __restrict__ W,
                                                     const float* __restrict__ bias) {
    gemm_core<256, false, true>(A, W, bias, g_qh, QK_SCALE);
}
__global__ __launch_bounds__(256) void gemm_kv_kernel(const float* __restrict__ A,
                                                      const float* __restrict__ W,
                                                      const float* __restrict__ bias) {
    gemm_core<512, false, true>(A, W, bias, g_kvh, 1.0f);
}
__global__ __launch_bounds__(256) void gemm_proj_kernel(const float* __restrict__ W,
                                                        const float* __restrict__ bias,
                                                        float* __restrict__ C) {
    gemm_core<256, true, false>(g_atth, W, bias, C, 1.0f);
}

// ---------------------------------------------------------------------------
// Fused attention: one block per (b, h); 64 threads (2 warps); loops t=0,1.
// Warp w owns rows [32w, 32w+32): 32x64 logits tile, 32x32 output tile.
// smem (halves): QS 64x40 (loaded once), KS 64x40, VT 32x72, P 64x72.
// ---------------------------------------------------------------------------
#define QS(r, c)  smh[(r) * 40 + (c)]
#define KS(r, c)  smh[2560 + (r) * 40 + (c)]
#define VT(n, k)  smh[5120 + (n) * 72 + (k)]
#define PSH(r, c) smh[7424 + (r) * 72 + (c)]

__global__ __launch_bounds__(64) void attn_kernel() {
    __shared__ __align__(16) __half smh[7424 + 64 * 72];   // 24064 B

    const int bid = blockIdx.x;
    const int h = bid & 7;
    const int b = bid >> 3;
    const int tid = threadIdx.x;
    const int warp = tid >> 5, lane = tid & 31;
    const int tg = lane & 3, gp = lane >> 2;
    const int row0 = warp * 32;
    const float* bh = g_bias + h * 4096;

    const __half* qptr = g_qh + ((long long)b * NTOK) * CDIM + h * HDIM;

    // q tile: loaded once, reused for both t (already scaled by q-GEMM)
#pragma unroll
    for (int i = 0; i < 4; i++) {
        int idx = tid + i * 64;
        int r = idx >> 2, c = (idx & 3) * 8;
        *(uint4*)&QS(r, c) = *(const uint4*)(qptr + (long long)r * CDIM + c);
    }

#pragma unroll 1
    for (int t = 0; t < T_SZ; t++) {
        const __half* kptr = g_kvh + (((long long)b * T_SZ + t) * NTOK) * (2 * CDIM) + h * HDIM;
        const __half* vptr = kptr + CDIM;

        // K (row-major) and V (transposed) tiles for this t
#pragma unroll
        for (int i = 0; i < 4; i++) {
            int idx = tid + i * 64;
            int r = idx >> 2, c = (idx & 3) * 8;
            *(uint4*)&KS(r, c) = *(const uint4*)(kptr + (long long)r * (2 * CDIM) + c);
            uint4 v4 = *(const uint4*)(vptr + (long long)r * (2 * CDIM) + c);
            __half vtmp[8];
            *(uint4*)vtmp = v4;
#pragma unroll
            for (int j = 0; j < 8; j++) VT(c + j, r) = vtmp[j];
        }
        __syncthreads();

        // ---- logits: S = q_scaled @ k^T ; warp tile 32x64, k16 x 2 ----
        float s[2][8][4];
#pragma unroll
        for (int mt = 0; mt < 2; mt++)
#pragma unroll
            for (int nt = 0; nt < 8; nt++)
                s[mt][nt][0] = s[mt][nt][1] = s[mt][nt][2] = s[mt][nt][3] = 0.0f;

#pragma unroll
        for (int kk = 0; kk < HDIM; kk += 16) {
            uint32_t a[2][4];
#pragma unroll
            for (int mt = 0; mt < 2; mt++) {
                int r0 = row0 + mt * 16 + gp;
                a[mt][0] = *(const uint32_t*)&QS(r0, kk + tg * 2);
                a[mt][1] = *(const uint32_t*)&QS(r0 + 8, kk + tg * 2);
                a[mt][2] = *(const uint32_t*)&QS(r0, kk + tg * 2 + 8);
                a[mt][3] = *(const uint32_t*)&QS(r0 + 8, kk + tg * 2 + 8);
            }
#pragma unroll
            for (int nt = 0; nt < 8; nt++) {
                int m0 = nt * 8 + gp;
                uint32_t b0 = *(const uint32_t*)&KS(m0, kk + tg * 2);
                uint32_t b1 = *(const uint32_t*)&KS(m0, kk + tg * 2 + 8);
#pragma unroll
                for (int mt = 0; mt < 2; mt++)
                    mma_f16(s[mt][nt], a[mt], b0, b1);
            }
        }

        // ---- bias add + softmax (fp32, rows mt x {gp, gp+8}) ----
        float inv[2][2];
#pragma unroll
        for (int mt = 0; mt < 2; mt++) {
            const int r1 = row0 + mt * 16 + gp, r2 = r1 + 8;
            float m1 = -1e30f, m2 = -1e30f;
#pragma unroll
            for (int nt = 0; nt < 8; nt++) {
                int c = nt * 8 + tg * 2;
                float2 bb1 = *(const float2*)(bh + r1 * 64 + c);
                float2 bb2 = *(const float2*)(bh + r2 * 64 + c);
                s[mt][nt][0] += bb1.x;  s[mt][nt][1] += bb1.y;
                s[mt][nt][2] += bb2.x;  s[mt][nt][3] += bb2.y;
                m1 = fmaxf(m1, fmaxf(s[mt][nt][0], s[mt][nt][1]));
                m2 = fmaxf(m2, fmaxf(s[mt][nt][2], s[mt][nt][3]));
            }
            m1 = fmaxf(m1, __shfl_xor_sync(0xffffffffu, m1, 1));
            m1 = fmaxf(m1, __shfl_xor_sync(0xffffffffu, m1, 2));
            m2 = fmaxf(m2, __shfl_xor_sync(0xffffffffu, m2, 1));
            m2 = fmaxf(m2, __shfl_xor_sync(0xffffffffu, m2, 2));

            float sum1 = 0.0f, sum2 = 0.0f;
#pragma unroll
            for (int nt = 0; nt < 8; nt++) {
                s[mt][nt][0] = __expf(s[mt][nt][0] - m1);
                s[mt][nt][1] = __expf(s[mt][nt][1] - m1);
                s[mt][nt][2] = __expf(s[mt][nt][2] - m2);
                s[mt][nt][3] = __expf(s[mt][nt][3] - m2);
                sum1 += s[mt][nt][0] + s[mt][nt][1];
                sum2 += s[mt][nt][2] + s[mt][nt][3];
            }
            sum1 += __shfl_xor_sync(0xffffffffu, sum1, 1);
            sum1 += __shfl_xor_sync(0xffffffffu, sum1, 2);
            sum2 += __shfl_xor_sync(0xffffffffu, sum2, 1);
            sum2 += __shfl_xor_sync(0xffffffffu, sum2, 2);
            inv[mt][0] = 1.0f / sum1;
            inv[mt][1] = 1.0f / sum2;
        }

        // P -> smem (fp16); rows are warp-private
#pragma unroll
        for (int mt = 0; mt < 2; mt++) {
            const int r1 = row0 + mt * 16 + gp, r2 = r1 + 8;
#pragma unroll
            for (int nt = 0; nt < 8; nt++) {
                int c = nt * 8 + tg * 2;
                *(uint32_t*)&PSH(r1, c) = h2bits(s[mt][nt][0] * inv[mt][0],
                                                 s[mt][nt][1] * inv[mt][0]);
                *(uint32_t*)&PSH(r2, c) = h2bits(s[mt][nt][2] * inv[mt][1],
                                                 s[mt][nt][3] * inv[mt][1]);
            }
        }
        __syncwarp();

        // ---- O = P @ V  (warp: 32x64 @ 64x32), k16 x 4 ----
        float o[2][4][4];
#pragma unroll
        for (int mt = 0; mt < 2; mt++)
#pragma unroll
            for (int nt = 0; nt < 4; nt++)
                o[mt][nt][0] = o[mt][nt][1] = o[mt][nt][2] = o[mt][nt][3] = 0.0f;

#pragma unroll
        for (int kk = 0; kk < NTOK; kk += 16) {
            uint32_t a[2][4];
#pragma unroll
            for (int mt = 0; mt < 2; mt++) {
                int r0 = row0 + mt * 16 + gp;
                a[mt][0] = *(const uint32_t*)&PSH(r0, kk + tg * 2);
                a[mt][1] = *(const uint32_t*)&PSH(r0 + 8, kk + tg * 2);
                a[mt][2] = *(const uint32_t*)&PSH(r0, kk + tg * 2 + 8);
                a[mt][3] = *(const uint32_t*)&PSH(r0 + 8, kk + tg * 2 + 8);
            }
#pragma unroll
            for (int nt = 0; nt < 4; nt++) {
                int n0 = nt * 8 + gp;
                uint32_t b0 = *(const uint32_t*)&VT(n0, kk + tg * 2);
                uint32_t b1 = *(const uint32_t*)&VT(n0, kk + tg * 2 + 8);
#pragma unroll
                for (int mt = 0; mt < 2; mt++)
                    mma_f16(o[mt][nt], a[mt], b0, b1);
            }
        }

        // ---- store merged-head output (fp16) at col h*32 ----
        __half* op = g_atth + (((long long)b * T_SZ + t) * NTOK) * CDIM + h * HDIM;
#pragma unroll
        for (int mt = 0; mt < 2; mt++) {
            const int r1 = row0 + mt * 16 + gp, r2 = r1 + 8;
#pragma unroll
            for (int nt = 0; nt < 4; nt++) {
                int c = nt * 8 + tg * 2;
                *(uint32_t*)(op + (long long)r1 * CDIM + c) = h2bits(o[mt][nt][0], o[mt][nt][1]);
                *(uint32_t*)(op + (long long)r2 * CDIM + c) = h2bits(o[mt][nt][2], o[mt][nt][3]);
            }
        }

        // KS/VT (and PSH) are about to be overwritten for the next t
        __syncthreads();
    }
}

// ---------------------------------------------------------------------------
// Launch
// ---------------------------------------------------------------------------
extern "C" void kernel_launch(void* const* d_in, const int* in_sizes, int n_in,
                              void* d_out, int out_size) {
    const float* x      = (const float*)d_in[0];
    const float* memory = (const float*)d_in[1];
    const float* q_w    = (const float*)d_in[2];
    const float* q_b    = (const float*)d_in[3];
    const float* kv_w   = (const float*)d_in[4];
    const float* kv_b   = (const float*)d_in[5];
    const float* proj_w = (const float*)d_in[6];
    const float* proj_b = (const float*)d_in[7];
    const float* rpb    = (const float*)d_in[8];
    float* out = (float*)d_out;

    // (H,64,64) dense bias table (128 KB, L2-resident)
    bias_kernel<<<64, 64>>>(rpb);

    // q projection (scale folded in): (131072 x 256) @ (256 x 256)^T -> fp16
    gemm_q_kernel<<<dim3(1024, 2), 256>>>(x, q_w, q_b);

    // kv projection: (262144 x 256) @ (512 x 256)^T -> fp16
    gemm_kv_kernel<<<dim3(2048, 4), 256>>>(memory, kv_w, kv_b);

    // fused attention: one block per (b, h), loops t
    attn_kernel<<<B_SZ * NHEAD, 64>>>();

    // output projection: (262144 x 256) @ (256 x 256)^T -> fp32 d_out
    gemm_proj_kernel<<<dim3(2048, 2), 256>>>(proj_w, proj_b, out);
}

// round 16
// speedup vs baseline: 1.6810x; 1.0210x over previous
#include <cuda_runtime.h>
#include <cuda_fp16.h>
#include <cstdint>

// ---------------------------------------------------------------------------
// Problem constants: B=2048, T=2, N(tokens)=64, C=256, H=8, hd=32
// ---------------------------------------------------------------------------
#define B_SZ   2048
#define T_SZ   2
#define NTOK   64
#define CDIM   256
#define NHEAD  8
#define HDIM   32

#define QK_SCALE 0.17677669529663687f   // 1/sqrt(32)

// Scratch (allocation-free contract: __device__ globals) — all fp16
__device__ __half g_qh  [33554432];   // (B*N, C)     q projection * scale
__device__ __half g_kvh [134217728];  // (B*T*N, 2C)  kv projection
__device__ __half g_atth[67108864];   // (B*T*N, C)   attention output
__device__ float  g_bias[32768];      // (H, N, N)

// ---------------------------------------------------------------------------
// Helpers
// ---------------------------------------------------------------------------
__device__ __forceinline__ void mma_f16(float (&d)[4], const uint32_t (&a)[4],
                                        uint32_t b0, uint32_t b1) {
    asm volatile(
        "mma.sync.aligned.m16n8k16.row.col.f32.f16.f16.f32 "
        "{%0,%1,%2,%3}, {%4,%5,%6,%7}, {%8,%9}, {%0,%1,%2,%3};\n"
        : "+f"(d[0]), "+f"(d[1]), "+f"(d[2]), "+f"(d[3])
        : "r"(a[0]), "r"(a[1]), "r"(a[2]), "r"(a[3]), "r"(b0), "r"(b1));
}

__device__ __forceinline__ uint2 h4pack(float4 v) {
    __half2 lo = __floats2half2_rn(v.x, v.y);
    __half2 hi = __floats2half2_rn(v.z, v.w);
    uint2 u;
    u.x = *reinterpret_cast<uint32_t*>(&lo);
    u.y = *reinterpret_cast<uint32_t*>(&hi);
    return u;
}

__device__ __forceinline__ uint32_t h2bits(float a, float b) {
    __half2 h = __floats2half2_rn(a, b);
    return *reinterpret_cast<uint32_t*>(&h);
}

// ---------------------------------------------------------------------------
// Relative position bias table -> dense (H, 64, 64)
// ---------------------------------------------------------------------------
__global__ void bias_kernel(const float* __restrict__ rpb) {
    int n = blockIdx.x;    // query token
    int m = threadIdx.x;   // key token
    int in_ = n >> 3, jn = n & 7;
    int im  = m >> 3, jm = m & 7;
    int idx = (in_ - im + 7) * 15 + (jn - jm + 7);
#pragma unroll
    for (int h = 0; h < NHEAD; h++)
        g_bias[h * 4096 + n * 64 + m] = rpb[idx * NHEAD + h];
}

// ---------------------------------------------------------------------------
// fp16 GEMM: C[M,N] = (A[M,256] * W[N,256]^T + bias[N]) * outScale
// A may be fp32 (converted while staging) or fp16 (direct). Output fp16/fp32.
// Block tile 128x128, BK=32, 256 threads = 8 warps (2m x 4n), warp 64x32.
// ---------------------------------------------------------------------------
template <int N, bool AHALF, bool OHALF>
__device__ __forceinline__ void gemm_core(const void* __restrict__ Av,
                                          const float* __restrict__ W,
                                          const float* __restrict__ bias,
                                          void* __restrict__ Cv,
                                          float outScale) {
    constexpr int K = 256;
    __shared__ __align__(16) __half As[128][40];   // 32 k + 8 pad
    __shared__ __align__(16) __half Bs[128][40];

    const float*  Af = (const float*)Av;
    const __half* Ah = (const __half*)Av;

    const int tid  = threadIdx.x;
    const int lane = tid & 31;
    const int warp = tid >> 5;
    const int wm = warp & 1, wn = warp >> 1;       // 2 x 4 warp grid
    const int tg = lane & 3, gp = lane >> 2;
    const long long rowBase = (long long)blockIdx.x * 128;
    const int colBase = blockIdx.y * 128;

    const int ldr = tid >> 3;          // 0..31
    const int ldc = (tid & 7) * 4;     // 4-element col within 32-wide k-tile

    float4 paf[4];
    uint2  pah[4];
    float4 pb[4];

    // prefetch kt = 0
#pragma unroll
    for (int i = 0; i < 4; i++) {
        int r = ldr + i * 32;
        if (AHALF) pah[i] = *(const uint2*)(Ah + (rowBase + r) * K + ldc);
        else       paf[i] = *(const float4*)(Af + (rowBase + r) * K + ldc);
        pb[i] = *(const float4*)(W + (long long)(colBase + r) * K + ldc);
    }

    float acc[4][4][4];
#pragma unroll
    for (int mt = 0; mt < 4; mt++)
#pragma unroll
        for (int nt = 0; nt < 4; nt++)
#pragma unroll
            for (int i = 0; i < 4; i++) acc[mt][nt][i] = 0.0f;

#pragma unroll 1
    for (int kt = 0; kt < K; kt += 32) {
        // stage -> smem as fp16
#pragma unroll
        for (int i = 0; i < 4; i++) {
            int r = ldr + i * 32;
            *(uint2*)&As[r][ldc] = AHALF ? pah[i] : h4pack(paf[i]);
            *(uint2*)&Bs[r][ldc] = h4pack(pb[i]);
        }
        __syncthreads();

        // prefetch next tile while computing
        if (kt + 32 < K) {
            const int ktn = kt + 32;
#pragma unroll
            for (int i = 0; i < 4; i++) {
                int r = ldr + i * 32;
                if (AHALF) pah[i] = *(const uint2*)(Ah + (rowBase + r) * K + ktn + ldc);
                else       paf[i] = *(const float4*)(Af + (rowBase + r) * K + ktn + ldc);
                pb[i] = *(const float4*)(W + (long long)(colBase + r) * K + ktn + ldc);
            }
        }

#pragma unroll
        for (int kk = 0; kk < 32; kk += 16) {
            uint32_t a[4][4];
#pragma unroll
            for (int mt = 0; mt < 4; mt++) {
                int r0 = wm * 64 + mt * 16 + gp;
                a[mt][0] = *(const uint32_t*)&As[r0][kk + tg * 2];
                a[mt][1] = *(const uint32_t*)&As[r0 + 8][kk + tg * 2];
                a[mt][2] = *(const uint32_t*)&As[r0][kk + tg * 2 + 8];
                a[mt][3] = *(const uint32_t*)&As[r0 + 8][kk + tg * 2 + 8];
            }
#pragma unroll
            for (int nt = 0; nt < 4; nt++) {
                int c0 = wn * 32 + nt * 8 + gp;
                uint32_t b0 = *(const uint32_t*)&Bs[c0][kk + tg * 2];
                uint32_t b1 = *(const uint32_t*)&Bs[c0][kk + tg * 2 + 8];
#pragma unroll
                for (int mt = 0; mt < 4; mt++)
                    mma_f16(acc[mt][nt], a[mt], b0, b1);
            }
        }
        __syncthreads();
    }

    // epilogue: bias (+scale) + store
#pragma unroll
    for (int mt = 0; mt < 4; mt++) {
        long long r0 = rowBase + wm * 64 + mt * 16 + gp;
#pragma unroll
        for (int nt = 0; nt < 4; nt++) {
            int c0 = colBase + wn * 32 + nt * 8 + tg * 2;
            float b0 = __ldg(bias + c0), b1 = __ldg(bias + c0 + 1);
            float v0 = (acc[mt][nt][0] + b0) * outScale;
            float v1 = (acc[mt][nt][1] + b1) * outScale;
            float v2 = (acc[mt][nt][2] + b0) * outScale;
            float v3 = (acc[mt][nt][3] + b1) * outScale;
            if (OHALF) {
                __half* C = (__half*)Cv;
                *(uint32_t*)(C + r0 * N + c0)       = h2bits(v0, v1);
                *(uint32_t*)(C + (r0 + 8) * N + c0) = h2bits(v2, v3);
            } else {
                float* C = (float*)Cv;
                *(float2*)(C + r0 * N + c0)       = make_float2(v0, v1);
                *(float2*)(C + (r0 + 8) * N + c0) = make_float2(v2, v3);
            }
        }
    }
}

__global__ __launch_bounds__(256) void gemm_q_kernel(const float* __restrict__ A,
                                                     const float* __restrict__ W,
                                                     const float* __restrict__ bias) {
    gemm_core<256, false, true>(A, W, bias, g_qh, QK_SCALE);
}
__global__ __launch_bounds__(256) void gemm_kv_kernel(const float* __restrict__ A,
                                                      const float* __restrict__ W,
                                                      const float* __restrict__ bias) {
    gemm_core<512, false, true>(A, W, bias, g_kvh, 1.0f);
}
__global__ __launch_bounds__(256) void gemm_proj_kernel(const float* __restrict__ W,
                                                        const float* __restrict__ bias,
                                                        float* __restrict__ C) {
    gemm_core<256, true, false>(g_atth, W, bias, C, 1.0f);
}

// ---------------------------------------------------------------------------
// Fused attention: one block per (b, h); 64 threads (2 warps); loops t=0,1.
// Warp w owns rows [32w, 32w+32): 32x64 logits tile, 32x32 output tile.
// P never touches smem: the QK C-fragment layout IS the PV A-fragment layout
// (same (gp,tg) keying), so P fragments are packed in registers.
// smem (halves): QS 64x40 (loaded once), KS 64x40, VT 32x72.  14848 B total.
// ---------------------------------------------------------------------------
#define QS(r, c)  smh[(r) * 40 + (c)]
#define KS(r, c)  smh[2560 + (r) * 40 + (c)]
#define VT(n, k)  smh[5120 + (n) * 72 + (k)]

__global__ __launch_bounds__(64) void attn_kernel() {
    __shared__ __align__(16) __half smh[7424];   // 14848 B

    const int bid = blockIdx.x;
    const int h = bid & 7;
    const int b = bid >> 3;
    const int tid = threadIdx.x;
    const int warp = tid >> 5, lane = tid & 31;
    const int tg = lane & 3, gp = lane >> 2;
    const int row0 = warp * 32;
    const float* bh = g_bias + h * 4096;

    const __half* qptr = g_qh + ((long long)b * NTOK) * CDIM + h * HDIM;

    // q tile: loaded once, reused for both t (already scaled by q-GEMM)
#pragma unroll
    for (int i = 0; i < 4; i++) {
        int idx = tid + i * 64;
        int r = idx >> 2, c = (idx & 3) * 8;
        *(uint4*)&QS(r, c) = *(const uint4*)(qptr + (long long)r * CDIM + c);
    }

#pragma unroll 1
    for (int t = 0; t < T_SZ; t++) {
        const __half* kptr = g_kvh + (((long long)b * T_SZ + t) * NTOK) * (2 * CDIM) + h * HDIM;
        const __half* vptr = kptr + CDIM;

        // K (row-major) and V (transposed) tiles for this t
#pragma unroll
        for (int i = 0; i < 4; i++) {
            int idx = tid + i * 64;
            int r = idx >> 2, c = (idx & 3) * 8;
            *(uint4*)&KS(r, c) = *(const uint4*)(kptr + (long long)r * (2 * CDIM) + c);
            uint4 v4 = *(const uint4*)(vptr + (long long)r * (2 * CDIM) + c);
            __half vtmp[8];
            *(uint4*)vtmp = v4;
#pragma unroll
            for (int j = 0; j < 8; j++) VT(c + j, r) = vtmp[j];
        }
        __syncthreads();

        // ---- logits: S = q_scaled @ k^T ; warp tile 32x64, k16 x 2 ----
        float s[2][8][4];
#pragma unroll
        for (int mt = 0; mt < 2; mt++)
#pragma unroll
            for (int nt = 0; nt < 8; nt++)
                s[mt][nt][0] = s[mt][nt][1] = s[mt][nt][2] = s[mt][nt][3] = 0.0f;

#pragma unroll
        for (int kk = 0; kk < HDIM; kk += 16) {
            uint32_t a[2][4];
#pragma unroll
            for (int mt = 0; mt < 2; mt++) {
                int r0 = row0 + mt * 16 + gp;
                a[mt][0] = *(const uint32_t*)&QS(r0, kk + tg * 2);
                a[mt][1] = *(const uint32_t*)&QS(r0 + 8, kk + tg * 2);
                a[mt][2] = *(const uint32_t*)&QS(r0, kk + tg * 2 + 8);
                a[mt][3] = *(const uint32_t*)&QS(r0 + 8, kk + tg * 2 + 8);
            }
#pragma unroll
            for (int nt = 0; nt < 8; nt++) {
                int m0 = nt * 8 + gp;
                uint32_t b0 = *(const uint32_t*)&KS(m0, kk + tg * 2);
                uint32_t b1 = *(const uint32_t*)&KS(m0, kk + tg * 2 + 8);
#pragma unroll
                for (int mt = 0; mt < 2; mt++)
                    mma_f16(s[mt][nt], a[mt], b0, b1);
            }
        }

        // ---- bias add + softmax (fp32, rows mt x {gp, gp+8}) ----
        float inv[2][2];
#pragma unroll
        for (int mt = 0; mt < 2; mt++) {
            const int r1 = row0 + mt * 16 + gp, r2 = r1 + 8;
            float m1 = -1e30f, m2 = -1e30f;
#pragma unroll
            for (int nt = 0; nt < 8; nt++) {
                int c = nt * 8 + tg * 2;
                float2 bb1 = *(const float2*)(bh + r1 * 64 + c);
                float2 bb2 = *(const float2*)(bh + r2 * 64 + c);
                s[mt][nt][0] += bb1.x;  s[mt][nt][1] += bb1.y;
                s[mt][nt][2] += bb2.x;  s[mt][nt][3] += bb2.y;
                m1 = fmaxf(m1, fmaxf(s[mt][nt][0], s[mt][nt][1]));
                m2 = fmaxf(m2, fmaxf(s[mt][nt][2], s[mt][nt][3]));
            }
            m1 = fmaxf(m1, __shfl_xor_sync(0xffffffffu, m1, 1));
            m1 = fmaxf(m1, __shfl_xor_sync(0xffffffffu, m1, 2));
            m2 = fmaxf(m2, __shfl_xor_sync(0xffffffffu, m2, 1));
            m2 = fmaxf(m2, __shfl_xor_sync(0xffffffffu, m2, 2));

            float sum1 = 0.0f, sum2 = 0.0f;
#pragma unroll
            for (int nt = 0; nt < 8; nt++) {
                s[mt][nt][0] = __expf(s[mt][nt][0] - m1);
                s[mt][nt][1] = __expf(s[mt][nt][1] - m1);
                s[mt][nt][2] = __expf(s[mt][nt][2] - m2);
                s[mt][nt][3] = __expf(s[mt][nt][3] - m2);
                sum1 += s[mt][nt][0] + s[mt][nt][1];
                sum2 += s[mt][nt][2] + s[mt][nt][3];
            }
            sum1 += __shfl_xor_sync(0xffffffffu, sum1, 1);
            sum1 += __shfl_xor_sync(0xffffffffu, sum1, 2);
            sum2 += __shfl_xor_sync(0xffffffffu, sum2, 1);
            sum2 += __shfl_xor_sync(0xffffffffu, sum2, 2);
            inv[mt][0] = 1.0f / sum1;
            inv[mt][1] = 1.0f / sum2;
        }

        // ---- P fragments packed in registers (no smem, no sync) ----
        // ph[mt][nt][0] = rows gp   of S-tile nt; ph[mt][nt][1] = rows gp+8
        uint32_t ph[2][8][2];
#pragma unroll
        for (int mt = 0; mt < 2; mt++)
#pragma unroll
            for (int nt = 0; nt < 8; nt++) {
                ph[mt][nt][0] = h2bits(s[mt][nt][0] * inv[mt][0],
                                       s[mt][nt][1] * inv[mt][0]);
                ph[mt][nt][1] = h2bits(s[mt][nt][2] * inv[mt][1],
                                       s[mt][nt][3] * inv[mt][1]);
            }

        // ---- O = P @ V  (warp: 32x64 @ 64x32), k16 x 4, A from ph ----
        float o[2][4][4];
#pragma unroll
        for (int mt = 0; mt < 2; mt++)
#pragma unroll
            for (int nt = 0; nt < 4; nt++)
                o[mt][nt][0] = o[mt][nt][1] = o[mt][nt][2] = o[mt][nt][3] = 0.0f;

#pragma unroll
        for (int kk = 0; kk < NTOK; kk += 16) {
            const int pt = kk >> 3;            // S-tile index for k = kk..kk+7
            uint32_t a[2][4];
#pragma unroll
            for (int mt = 0; mt < 2; mt++) {
                a[mt][0] = ph[mt][pt][0];      // (row gp,   k=kk+2tg..+1)
                a[mt][1] = ph[mt][pt][1];      // (row gp+8, k=kk+2tg..+1)
                a[mt][2] = ph[mt][pt + 1][0];  // (row gp,   k=kk+8+2tg..+1)
                a[mt][3] = ph[mt][pt + 1][1];  // (row gp+8, k=kk+8+2tg..+1)
            }
#pragma unroll
            for (int nt = 0; nt < 4; nt++) {
                int n0 = nt * 8 + gp;
                uint32_t b0 = *(const uint32_t*)&VT(n0, kk + tg * 2);
                uint32_t b1 = *(const uint32_t*)&VT(n0, kk + tg * 2 + 8);
#pragma unroll
                for (int mt = 0; mt < 2; mt++)
                    mma_f16(o[mt][nt], a[mt], b0, b1);
            }
        }

        // ---- store merged-head output (fp16) at col h*32 ----
        __half* op = g_atth + (((long long)b * T_SZ + t) * NTOK) * CDIM + h * HDIM;
#pragma unroll
        for (int mt = 0; mt < 2; mt++) {
            const int r1 = row0 + mt * 16 + gp, r2 = r1 + 8;
#pragma unroll
            for (int nt = 0; nt < 4; nt++) {
                int c = nt * 8 + tg * 2;
                *(uint32_t*)(op + (long long)r1 * CDIM + c) = h2bits(o[mt][nt][0], o[mt][nt][1]);
                *(uint32_t*)(op + (long long)r2 * CDIM + c) = h2bits(o[mt][nt][2], o[mt][nt][3]);
            }
        }

        // KS/VT are about to be overwritten for the next t
        __syncthreads();
    }
}

// ---------------------------------------------------------------------------
// Launch
// ---------------------------------------------------------------------------
extern "C" void kernel_launch(void* const* d_in, const int* in_sizes, int n_in,
                              void* d_out, int out_size) {
    const float* x      = (const float*)d_in[0];
    const float* memory = (const float*)d_in[1];
    const float* q_w    = (const float*)d_in[2];
    const float* q_b    = (const float*)d_in[3];
    const float* kv_w   = (const float*)d_in[4];
    const float* kv_b   = (const float*)d_in[5];
    const float* proj_w = (const float*)d_in[6];
    const float* proj_b = (const float*)d_in[7];
    const float* rpb    = (const float*)d_in[8];
    float* out = (float*)d_out;

    // (H,64,64) dense bias table (128 KB, L2-resident)
    bias_kernel<<<64, 64>>>(rpb);

    // q projection (scale folded in): (131072 x 256) @ (256 x 256)^T -> fp16
    gemm_q_kernel<<<dim3(1024, 2), 256>>>(x, q_w, q_b);

    // kv projection: (262144 x 256) @ (512 x 256)^T -> fp16
    gemm_kv_kernel<<<dim3(2048, 4), 256>>>(memory, kv_w, kv_b);

    // fused attention: one block per (b, h), loops t
    attn_kernel<<<B_SZ * NHEAD, 64>>>();

    // output projection: (262144 x 256) @ (256 x 256)^T -> fp32 d_out
    gemm_proj_kernel<<<dim3(2048, 2), 256>>>(proj_w, proj_b, out);
}